// round 15
// baseline (speedup 1.0000x reference)
#include <cuda_runtime.h>
#include <cstdint>

#define BATCH   8
#define NANCH   25200
#define NCH     85
#define TOPK    1000
#define KPAD    1024
#define NCLS    80
#define CONF_TH 0.25f
#define IOU_TH  0.45f
#define MAX_WH  4096.0f
#define NB14    16384
#define CAP     8192

// ---------------- scratch (device globals; no allocation) ----------------
__device__ unsigned           g_enc [BATCH * NANCH];
__device__ unsigned           g_hist[BATCH * NB14];   // zeroed by k_pick after use
__device__ unsigned long long g_cand[BATCH * CAP];
__device__ unsigned           g_ccnt[BATCH];          // zeroed by k_post after use
__device__ unsigned           g_bucket[BATCH];
__device__ unsigned           g_need[BATCH];
__device__ unsigned long long g_T64[BATCH];           // 0 = needs rank step

// ---------------- K1: score = obj * max(cls); encode; fused 14-bit histogram ----------------
#define SB 128
__global__ void __launch_bounds__(SB) k_score(const float* __restrict__ x) {
    __shared__ float sx[SB * NCH];
    const int tid = threadIdx.x;
    const size_t base = (size_t)blockIdx.x * SB * NCH;
    const float4* xv = (const float4*)(x + base);
    float4* sv = (float4*)sx;
    #pragma unroll
    for (int t = tid; t < SB * NCH / 4; t += SB) sv[t] = xv[t];
    __syncthreads();

    const int a = blockIdx.x * SB + tid;
    const float* p = sx + tid * NCH;
    const float obj = p[4];

    const int off = tid * NCH + 5;
    const int pre = (-off) & 3;
    float m0 = __int_as_float(0xff800000);
    for (int k = 0; k < pre; ++k) m0 = fmaxf(m0, sx[off + k]);
    const int a0  = off + pre;
    const int n   = 80 - pre;
    const int nf4 = n >> 2;
    const int tl  = n & 3;
    const float4* pv = (const float4*)(sx + a0);
    float4 acc = pv[0];
    #pragma unroll 4
    for (int q = 1; q < nf4; ++q) {
        float4 v = pv[q];
        acc.x = fmaxf(acc.x, v.x); acc.y = fmaxf(acc.y, v.y);
        acc.z = fmaxf(acc.z, v.z); acc.w = fmaxf(acc.w, v.w);
    }
    float m = fmaxf(fmaxf(acc.x, acc.y), fmaxf(acc.z, acc.w));
    m = fmaxf(m, m0);
    const int tb = a0 + 4 * nf4;
    for (int k = 0; k < tl; ++k) m = fmaxf(m, sx[tb + k]);

    float sc = __fmul_rn(obj, m);
    unsigned u = __float_as_uint((sc > CONF_TH) ? sc : -1.0f);
    unsigned e = (u & 0x80000000u) ? ~u : (u | 0x80000000u);
    g_enc[a] = e;

    int b = a / NANCH;
    unsigned addr = (unsigned)b * NB14 + (e >> 18);
    unsigned mm = __match_any_sync(0xffffffffu, addr);
    if ((tid & 31) == (__ffs(mm) - 1))
        atomicAdd(&g_hist[addr], (unsigned)__popc(mm));
}

// ---------------- K2a: boundary bucket via register suffix scan ----------------
__global__ void __launch_bounds__(1024) k_pick() {
    const int b = blockIdx.x, tid = threadIdx.x;
    const int wid = tid >> 5, lane = tid & 31;
    __shared__ unsigned s_w[32];

    unsigned lv[16];
    const uint4* hv = (const uint4*)(g_hist + b * NB14 + tid * 16);
    #pragma unroll
    for (int q = 0; q < 4; ++q) {
        uint4 h = hv[q];
        lv[q * 4 + 0] = h.x; lv[q * 4 + 1] = h.y;
        lv[q * 4 + 2] = h.z; lv[q * 4 + 3] = h.w;
    }
    uint4* hz = (uint4*)(g_hist + b * NB14 + tid * 16);
    const uint4 z4 = make_uint4(0u, 0u, 0u, 0u);
    #pragma unroll
    for (int q = 0; q < 4; ++q) hz[q] = z4;

    unsigned run = 0;
    #pragma unroll
    for (int i = 15; i >= 0; --i) { run += lv[i]; lv[i] = run; }
    const unsigned ttot = run;
    unsigned v = ttot;
    #pragma unroll
    for (int off = 1; off < 32; off <<= 1) {
        unsigned t = __shfl_down_sync(0xffffffffu, v, off);
        if (lane + off < 32) v += t;
    }
    if (lane == 0) s_w[wid] = v;
    __syncthreads();
    if (tid < 32) {
        unsigned u0 = s_w[tid], w = u0;
        #pragma unroll
        for (int off = 1; off < 32; off <<= 1) {
            unsigned t = __shfl_down_sync(0xffffffffu, w, off);
            if (tid + off < 32) w += t;
        }
        s_w[tid] = w - u0;
    }
    __syncthreads();
    {
        const int base16 = tid * 16;
        unsigned above = s_w[wid] + (v - ttot);
        #pragma unroll
        for (int i = 0; i < 16; ++i) {
            unsigned tot = above + lv[i];
            unsigned cnt = lv[i] - ((i < 15) ? lv[i + 1] : 0u);
            unsigned gt  = tot - cnt;
            if (gt < TOPK && TOPK <= tot) {
                unsigned need = TOPK - gt;
                g_bucket[b] = (unsigned)(base16 + i);
                g_need[b]   = need;
                g_T64[b]    = (need == cnt)
                              ? ((unsigned long long)(base16 + i) << 50) : 0ull;
            }
        }
    }
}

// ---------------- K2b: compact boundary-bucket candidates (grid-wide) ----------------
__global__ void __launch_bounds__(1024) k_cand() {
    const int b = blockIdx.y;
    const int i = blockIdx.x * 1024 + threadIdx.x;
    if (i >= NANCH) return;
    unsigned e = g_enc[b * NANCH + i];
    if ((e >> 18) == g_bucket[b]) {
        unsigned pos = atomicAdd(&g_ccnt[b], 1u);
        if (pos < CAP)
            g_cand[b * CAP + pos] =
                ((unsigned long long)e << 32) | (unsigned)(~(unsigned)i);
    }
}

// ---------------- bitonic shfl stage helper (descending network) ----------------
__device__ __forceinline__ unsigned long long bsort_shfl_stage(
    unsigned long long v, int tid, unsigned kk, unsigned j) {
    unsigned long long pv = __shfl_xor_sync(0xffffffffu, v, j);
    bool upper = (tid & j) != 0;
    bool desc  = ((tid & kk) == 0);
    bool takemax = (desc != upper);
    bool pgt = pv > v;
    return (takemax == pgt) ? pv : v;
}

// ---------------- K3: rank + collect + sort + gather + class-decomposed NMS + output ----------------
#define PO_SC     0         // scratch union: cand u64[CAP] | hist2 | scn2
#define PO_HIST2  65536
#define PO_SCN2   73728
#define PO_OUTK   81920     // u64[1024]
#define PO_BOXO   90112     // float4[1024]
#define PO_BOXP   106496    // float4[1024]
#define PO_AREA   122880    // float[1024]
#define PO_SCORE  126976    // float[1024]
#define PO_CLSF   131072    // float[1024]
#define PO_SIDX   135168    // int[1024]
#define PO_SCLS   139264    // int[1024]
#define PO_CLIST  143360    // int[1024]  ordered per-class members
#define PO_KL     147456    // int[1024]  per-class kept lists (slices at cbase)
#define PO_KEEPB  151552    // u32[1024]
#define PO_CBIT   155648    // u32[NCLS*32] = 10240
#define PO_CBASE  165888    // int[NCLS+1]
#define K3_SMEM   166400

__global__ void __launch_bounds__(1024) k_post(const float* __restrict__ x,
                                               float* __restrict__ out) {
    const int b   = blockIdx.x;
    const int tid = threadIdx.x;
    const int wid = tid >> 5, lane = tid & 31;
    extern __shared__ unsigned char sm[];
    unsigned long long* cand  = (unsigned long long*)(sm + PO_SC);
    unsigned*           hist2 = (unsigned*)(sm + PO_HIST2);
    unsigned*           scn2  = (unsigned*)(sm + PO_SCN2);
    unsigned long long* outk  = (unsigned long long*)(sm + PO_OUTK);
    float4*   boxo  = (float4*)  (sm + PO_BOXO);
    float4*   boxp  = (float4*)  (sm + PO_BOXP);
    float*    area  = (float*)   (sm + PO_AREA);
    float*    score = (float*)   (sm + PO_SCORE);
    float*    clsf  = (float*)   (sm + PO_CLSF);
    int*      sidx  = (int*)     (sm + PO_SIDX);
    int*      scls  = (int*)     (sm + PO_SCLS);
    int*      clist = (int*)     (sm + PO_CLIST);
    int*      kl    = (int*)     (sm + PO_KL);
    unsigned* keepb = (unsigned*)(sm + PO_KEEPB);
    unsigned* cbit  = (unsigned*)(sm + PO_CBIT);
    int*      cbase = (int*)     (sm + PO_CBASE);
    __shared__ unsigned s_ctrl[4];
    __shared__ unsigned long long s_T64;

    const unsigned* encb = g_enc + b * NANCH;

    // ---- Phase 1: exact 1000th key T64 ----
    unsigned long long T64 = g_T64[b];
    if (T64 == 0ull) {
        unsigned M0 = g_ccnt[b];
        unsigned need = g_need[b];
        unsigned C;
        if (M0 <= CAP) {
            C = M0;
            for (unsigned j = tid; j < C; j += 1024) cand[j] = g_cand[b * CAP + j];
            __syncthreads();
        } else {
            unsigned long long prefix = (unsigned long long)g_bucket[b];
            int shift = 50;
            unsigned count = M0;
            while (count > CAP) {
                int w = (shift >= 11) ? 11 : shift;
                int s2 = shift - w;
                unsigned dmask = (1u << w) - 1u;
                for (int t = tid; t < 2048; t += 1024) hist2[t] = 0u;
                __syncthreads();
                for (int it = 0; it < 25; ++it) {
                    int i = tid + it * 1024;
                    if (i < NANCH) {
                        unsigned long long key =
                            ((unsigned long long)encb[i] << 32) | (unsigned)(~(unsigned)i);
                        if ((key >> shift) == prefix)
                            atomicAdd(&hist2[(unsigned)((key >> s2) & dmask)], 1u);
                    }
                }
                __syncthreads();
                for (int t = tid; t < 2048; t += 1024) scn2[t] = hist2[t];
                __syncthreads();
                for (int d = 1; d < 2048; d <<= 1) {
                    unsigned a0 = (tid + d < 2048) ? scn2[tid + d] : 0u;
                    unsigned a1 = (tid + 1024 + d < 2048) ? scn2[tid + 1024 + d] : 0u;
                    __syncthreads();
                    scn2[tid] += a0; scn2[tid + 1024] += a1;
                    __syncthreads();
                }
                #pragma unroll
                for (int q = 0; q < 2; ++q) {
                    int d = tid + q * 1024;
                    unsigned tot = scn2[d], gt = tot - hist2[d];
                    if (gt < need && need <= tot) {
                        s_ctrl[0] = (unsigned)d;
                        s_ctrl[1] = need - gt;
                        s_ctrl[2] = hist2[d];
                    }
                }
                __syncthreads();
                prefix = (prefix << w) | (unsigned long long)s_ctrl[0];
                need = s_ctrl[1]; count = s_ctrl[2]; shift = s2;
                __syncthreads();
            }
            if (tid == 0) s_ctrl[3] = 0u;
            __syncthreads();
            for (int it = 0; it < 25; ++it) {
                int i = tid + it * 1024;
                if (i < NANCH) {
                    unsigned long long key =
                        ((unsigned long long)encb[i] << 32) | (unsigned)(~(unsigned)i);
                    if ((key >> shift) == prefix) {
                        unsigned pos = atomicAdd(&s_ctrl[3], 1u);
                        if (pos < CAP) cand[pos] = key;
                    }
                }
            }
            __syncthreads();
            C = s_ctrl[3];
        }
        for (unsigned j = tid; j < C; j += 1024) {
            unsigned long long kj = cand[j];
            unsigned gt = 0;
            for (unsigned k = 0; k < C; ++k) gt += (cand[k] > kj);
            if (gt == need - 1) s_T64 = kj;
        }
        __syncthreads();
        T64 = s_T64;
    }

    // ---- Phase 2: collect the exactly-1000 keys >= T64 ----
    if (tid == 0) s_ctrl[3] = 0u;
    __syncthreads();
    #pragma unroll 5
    for (int it = 0; it < 25; ++it) {
        int i = tid + it * 1024;
        if (i < NANCH) {
            unsigned long long key =
                ((unsigned long long)encb[i] << 32) | (unsigned)(~(unsigned)i);
            if (key >= T64) {
                unsigned pos = atomicAdd(&s_ctrl[3], 1u);
                if (pos < KPAD) outk[pos] = key;
            }
        }
    }
    __syncthreads();
    const unsigned ncol = (s_ctrl[3] < KPAD) ? s_ctrl[3] : KPAD;
    if (tid >= (int)ncol) outk[tid] = 0ull;
    __syncthreads();

    // ---- Phase 3: hybrid bitonic sort 1024 desc ----
    {
        unsigned long long v = outk[tid];
        #pragma unroll
        for (unsigned kk = 2; kk <= 32; kk <<= 1)
            for (unsigned j = kk >> 1; j > 0; j >>= 1)
                v = bsort_shfl_stage(v, tid, kk, j);
        outk[tid] = v;
        __syncthreads();
        for (unsigned kk = 64; kk <= 1024; kk <<= 1) {
            for (unsigned j = kk >> 1; j >= 32; j >>= 1) {
                unsigned i = (unsigned)tid, ixj = i ^ j;
                if (ixj > i) {
                    unsigned long long a = outk[i], bb = outk[ixj];
                    bool desc = ((i & kk) == 0);
                    if (desc ? (a < bb) : (a > bb)) { outk[i] = bb; outk[ixj] = a; }
                }
                __syncthreads();
            }
            v = outk[tid];
            #pragma unroll
            for (unsigned j = 16; j > 0; j >>= 1)
                v = bsort_shfl_stage(v, tid, kk, j);
            outk[tid] = v;
            __syncthreads();
        }
    }

    // ---- Phase 4: decode; depth-2 pipelined warp-per-row gather + argmax ----
    if (tid < NCLS + 1) cbase[tid] = 0;
    for (int t = tid; t < NCLS * 32; t += 1024) cbit[t] = 0u;
    keepb[tid] = 0u;

    unsigned long long key = outk[tid];
    float sc = -1.0f;
    int   idx = -1;
    if (key != 0ull) {
        unsigned e = (unsigned)(key >> 32);
        unsigned u = (e & 0x80000000u) ? (e ^ 0x80000000u) : ~e;
        sc = __uint_as_float(u);
        idx = (int)(~(unsigned)(key & 0xffffffffull));
    }
    score[tid] = sc;
    sidx[tid]  = (tid < TOPK) ? idx : -1;
    scls[tid]  = -1;
    boxp[tid] = make_float4(0.f, 0.f, 0.f, 0.f);
    boxo[tid] = make_float4(0.f, 0.f, 0.f, 0.f);
    area[tid] = 0.f; clsf[tid] = 0.f;
    __syncthreads();

    {
        int r = wid;
        float a0v = 0.f, a1v = 0.f, a2v = 0.f;
        float b0v = 0.f, b1v = 0.f, b2v = 0.f;
        if (r < TOPK && sidx[r] >= 0) {
            const float* p = x + ((size_t)b * NANCH + sidx[r]) * NCH;
            a0v = p[lane]; a1v = p[32 + lane];
            a2v = (lane < 21) ? p[64 + lane] : 0.0f;
        }
        if (r + 32 < TOPK && sidx[r + 32] >= 0) {
            const float* p = x + ((size_t)b * NANCH + sidx[r + 32]) * NCH;
            b0v = p[lane]; b1v = p[32 + lane];
            b2v = (lane < 21) ? p[64 + lane] : 0.0f;
        }
        while (r < TOPK) {
            int rn = r + 64;
            float n0 = 0.f, n1 = 0.f, n2 = 0.f;
            if (rn < TOPK && sidx[rn] >= 0) {
                const float* pn = x + ((size_t)b * NANCH + sidx[rn]) * NCH;
                n0 = pn[lane]; n1 = pn[32 + lane];
                n2 = (lane < 21) ? pn[64 + lane] : 0.0f;
            }
            if (sidx[r] >= 0) {
                float best = __int_as_float(0xff800000);
                int   bi   = 1 << 30;
                if (lane >= 5)                { best = a0v; bi = lane - 5;  }
                if (a1v > best)               { best = a1v; bi = 27 + lane; }
                if (lane < 21 && a2v > best)  { best = a2v; bi = 59 + lane; }
                #pragma unroll
                for (int o = 16; o; o >>= 1) {
                    float ov = __shfl_down_sync(0xffffffffu, best, o);
                    int   oi = __shfl_down_sync(0xffffffffu, bi, o);
                    if (ov > best || (ov == best && oi < bi)) { best = ov; bi = oi; }
                }
                float cx = __shfl_sync(0xffffffffu, a0v, 0);
                float cy = __shfl_sync(0xffffffffu, a0v, 1);
                float w  = __shfl_sync(0xffffffffu, a0v, 2);
                float h  = __shfl_sync(0xffffffffu, a0v, 3);
                if (lane == 0) {
                    float hw = __fmul_rn(w, 0.5f), hh = __fmul_rn(h, 0.5f);
                    float x1 = __fsub_rn(cx, hw), y1 = __fsub_rn(cy, hh);
                    float x2 = __fadd_rn(cx, hw), y2 = __fadd_rn(cy, hh);
                    float cf = (float)bi;
                    float o2 = __fmul_rn(cf, MAX_WH);
                    float ox1 = __fadd_rn(x1, o2), oy1 = __fadd_rn(y1, o2);
                    float ox2 = __fadd_rn(x2, o2), oy2 = __fadd_rn(y2, o2);
                    boxp[r] = make_float4(x1, y1, x2, y2);
                    boxo[r] = make_float4(ox1, oy1, ox2, oy2);
                    area[r] = __fmul_rn(__fsub_rn(ox2, ox1), __fsub_rn(oy2, oy1));
                    clsf[r] = cf;
                    scls[r] = bi;
                }
            }
            r += 32;
            a0v = b0v; a1v = b1v; a2v = b2v;
            b0v = n0;  b1v = n1;  b2v = n2;
        }
    }
    __syncthreads();

    // only VALID rows participate in classes (invalid never kept, never suppress)
    const int c = (tid < TOPK && score[tid] > CONF_TH) ? scls[tid] : -1;

    // ---- Phase 5: ordered per-class member lists (deterministic ranks) ----
    if (c >= 0) atomicOr(&cbit[c * 32 + (tid >> 5)], 1u << lane);
    __syncthreads();
    if (tid < NCLS) {                 // per-class counts
        unsigned cnt = 0;
        #pragma unroll 8
        for (int w = 0; w < 32; ++w) cnt += __popc(cbit[tid * 32 + w]);
        cbase[tid + 1] = (int)cnt;    // store count at +1; prefix below
    }
    __syncthreads();
    if (tid == 0) {
        int run = 0;
        #pragma unroll
        for (int k = 0; k < NCLS; ++k) { int t = cbase[k + 1]; cbase[k + 1] = 0; cbase[k] = run; run += t; cbase[k + 1] = run; }
        // after loop: cbase[k] = exclusive prefix, cbase[NCLS] = total
    }
    __syncthreads();
    if (c >= 0) {
        const int w0 = tid >> 5;
        unsigned r = 0;
        for (int w = 0; w < w0; ++w) r += __popc(cbit[c * 32 + w]);
        r += __popc(cbit[c * 32 + w0] & ((1u << lane) - 1u));
        clist[cbase[c] + r] = tid;
    }
    __syncthreads();

    // ---- Phase 6: class-decomposed greedy NMS, warp per class (fused IoU) ----
    for (int cc = wid; cc < NCLS; cc += 32) {
        int base = cbase[cc], m = cbase[cc + 1] - base;
        int nk = 0;
        for (int k = 0; k < m; ++k) {
            int j = clist[base + k];
            float4 bj = boxo[j];
            float  aj = area[j];
            bool sup = false;
            for (int q = lane; q < nk; q += 32) {
                int jk = kl[base + q];
                float4 bk = boxo[jk];
                float ww = fmaxf(__fsub_rn(fminf(bk.z, bj.z), fmaxf(bk.x, bj.x)), 0.0f);
                float hh = fmaxf(__fsub_rn(fminf(bk.w, bj.w), fmaxf(bk.y, bj.y)), 0.0f);
                float inter = __fmul_rn(ww, hh);
                float den = __fadd_rn(__fsub_rn(__fadd_rn(area[jk], aj), inter), 1e-9f);
                if (__fdiv_rn(inter, den) > IOU_TH) sup = true;
            }
            sup = __any_sync(0xffffffffu, sup);
            if (!sup) {
                if (lane == 0) { kl[base + nk] = j; keepb[j] = 1u; }
                nk++;
                __syncwarp();
            }
        }
    }
    __syncthreads();

    // ---- Phase 7: output + self-clean ----
    if (tid < TOPK) {
        bool keep = keepb[tid] != 0u;
        float4 bx = boxp[tid];
        float so  = score[tid];
        float cf  = clsf[tid];
        if (!keep) { bx = make_float4(0.f, 0.f, 0.f, 0.f); so = 0.f; cf = 0.f; }
        float* o = out + ((size_t)b * TOPK + tid) * 6;
        o[0] = bx.x; o[1] = bx.y; o[2] = bx.z; o[3] = bx.w; o[4] = so; o[5] = cf;
    }
    if (tid == 0) g_ccnt[b] = 0u;
}

// ---------------- launcher ----------------
extern "C" void kernel_launch(void* const* d_in, const int* in_sizes, int n_in,
                              void* d_out, int out_size) {
    (void)in_sizes; (void)n_in; (void)out_size;
    const float* x = (const float*)d_in[0];
    float* out = (float*)d_out;
    cudaFuncSetAttribute(k_post, cudaFuncAttributeMaxDynamicSharedMemorySize, K3_SMEM);

    k_score<<<(BATCH * NANCH) / SB, SB>>>(x);
    k_pick <<<BATCH, 1024>>>();
    k_cand <<<dim3(25, BATCH), 1024>>>();
    k_post <<<BATCH, 1024, K3_SMEM>>>(x, out);
}

// round 16
// speedup vs baseline: 1.1019x; 1.1019x over previous
#include <cuda_runtime.h>
#include <cstdint>

#define BATCH   8
#define NANCH   25200
#define NCH     85
#define TOPK    1000
#define KPAD    1024
#define NCLS    80
#define CONF_TH 0.25f
#define IOU_TH  0.45f
#define MAX_WH  4096.0f
#define NB14    16384
#define CAP     8192

// ---------------- scratch (device globals; no allocation) ----------------
__device__ unsigned           g_enc [BATCH * NANCH];
__device__ unsigned           g_hist[BATCH * NB14];   // zeroed by k_pick after use
__device__ unsigned long long g_cand[BATCH * CAP];
__device__ unsigned long long g_selk[BATCH * KPAD];
__device__ unsigned           g_ccnt[BATCH];          // zeroed by k_sel after use
__device__ unsigned           g_scnt[BATCH];          // zeroed by k_nmsout after use
__device__ unsigned           g_bucket[BATCH];
__device__ unsigned           g_need[BATCH];
__device__ unsigned long long g_T64[BATCH];           // 0 = needs rank step
// rank-ordered winner data (rows [0,TOPK) rewritten every run)
__device__ float  g_rscore[BATCH * KPAD];
__device__ float4 g_rboxp [BATCH * KPAD];
__device__ float4 g_rboxo [BATCH * KPAD];
__device__ float  g_rarea [BATCH * KPAD];
__device__ int    g_rcls  [BATCH * KPAD];

// ---------------- K1: score = obj * max(cls); encode; fused 14-bit histogram ----------------
#define SB 128
__global__ void __launch_bounds__(SB) k_score(const float* __restrict__ x) {
    __shared__ float sx[SB * NCH];
    const int tid = threadIdx.x;
    const size_t base = (size_t)blockIdx.x * SB * NCH;
    const float4* xv = (const float4*)(x + base);
    float4* sv = (float4*)sx;
    #pragma unroll
    for (int t = tid; t < SB * NCH / 4; t += SB) sv[t] = xv[t];
    __syncthreads();

    const int a = blockIdx.x * SB + tid;
    const float* p = sx + tid * NCH;
    const float obj = p[4];

    const int off = tid * NCH + 5;
    const int pre = (-off) & 3;
    float m0 = __int_as_float(0xff800000);
    for (int k = 0; k < pre; ++k) m0 = fmaxf(m0, sx[off + k]);
    const int a0  = off + pre;
    const int n   = 80 - pre;
    const int nf4 = n >> 2;
    const int tl  = n & 3;
    const float4* pv = (const float4*)(sx + a0);
    float4 acc = pv[0];
    #pragma unroll 4
    for (int q = 1; q < nf4; ++q) {
        float4 v = pv[q];
        acc.x = fmaxf(acc.x, v.x); acc.y = fmaxf(acc.y, v.y);
        acc.z = fmaxf(acc.z, v.z); acc.w = fmaxf(acc.w, v.w);
    }
    float m = fmaxf(fmaxf(acc.x, acc.y), fmaxf(acc.z, acc.w));
    m = fmaxf(m, m0);
    const int tb = a0 + 4 * nf4;
    for (int k = 0; k < tl; ++k) m = fmaxf(m, sx[tb + k]);

    float sc = __fmul_rn(obj, m);
    unsigned u = __float_as_uint((sc > CONF_TH) ? sc : -1.0f);
    unsigned e = (u & 0x80000000u) ? ~u : (u | 0x80000000u);
    g_enc[a] = e;

    int b = a / NANCH;
    unsigned addr = (unsigned)b * NB14 + (e >> 18);
    unsigned mm = __match_any_sync(0xffffffffu, addr);
    if ((tid & 31) == (__ffs(mm) - 1))
        atomicAdd(&g_hist[addr], (unsigned)__popc(mm));
}

// ---------------- K2a: boundary bucket via register suffix scan ----------------
__global__ void __launch_bounds__(1024) k_pick() {
    const int b = blockIdx.x, tid = threadIdx.x;
    const int wid = tid >> 5, lane = tid & 31;
    __shared__ unsigned s_w[32];

    unsigned lv[16];
    const uint4* hv = (const uint4*)(g_hist + b * NB14 + tid * 16);
    #pragma unroll
    for (int q = 0; q < 4; ++q) {
        uint4 h = hv[q];
        lv[q * 4 + 0] = h.x; lv[q * 4 + 1] = h.y;
        lv[q * 4 + 2] = h.z; lv[q * 4 + 3] = h.w;
    }
    uint4* hz = (uint4*)(g_hist + b * NB14 + tid * 16);
    const uint4 z4 = make_uint4(0u, 0u, 0u, 0u);
    #pragma unroll
    for (int q = 0; q < 4; ++q) hz[q] = z4;

    unsigned run = 0;
    #pragma unroll
    for (int i = 15; i >= 0; --i) { run += lv[i]; lv[i] = run; }
    const unsigned ttot = run;
    unsigned v = ttot;
    #pragma unroll
    for (int off = 1; off < 32; off <<= 1) {
        unsigned t = __shfl_down_sync(0xffffffffu, v, off);
        if (lane + off < 32) v += t;
    }
    if (lane == 0) s_w[wid] = v;
    __syncthreads();
    if (tid < 32) {
        unsigned u0 = s_w[tid], w = u0;
        #pragma unroll
        for (int off = 1; off < 32; off <<= 1) {
            unsigned t = __shfl_down_sync(0xffffffffu, w, off);
            if (tid + off < 32) w += t;
        }
        s_w[tid] = w - u0;
    }
    __syncthreads();
    {
        const int base16 = tid * 16;
        unsigned above = s_w[wid] + (v - ttot);
        #pragma unroll
        for (int i = 0; i < 16; ++i) {
            unsigned tot = above + lv[i];
            unsigned cnt = lv[i] - ((i < 15) ? lv[i + 1] : 0u);
            unsigned gt  = tot - cnt;
            if (gt < TOPK && TOPK <= tot) {
                unsigned need = TOPK - gt;
                g_bucket[b] = (unsigned)(base16 + i);
                g_need[b]   = need;
                g_T64[b]    = (need == cnt)
                              ? ((unsigned long long)(base16 + i) << 50) : 0ull;
            }
        }
    }
}

// ---------------- K2b: compact boundary-bucket candidates (grid-wide) ----------------
__global__ void __launch_bounds__(1024) k_cand() {
    const int b = blockIdx.y;
    if (g_T64[b] != 0ull) return;          // boundary already exact
    const int i = blockIdx.x * 1024 + threadIdx.x;
    if (i >= NANCH) return;
    unsigned e = g_enc[b * NANCH + i];
    if ((e >> 18) == g_bucket[b]) {
        unsigned pos = atomicAdd(&g_ccnt[b], 1u);
        if (pos < CAP)
            g_cand[b * CAP + pos] =
                ((unsigned long long)e << 32) | (unsigned)(~(unsigned)i);
    }
}

// ---------------- K2c: exact 1000th key via rank-by-count ----------------
#define SEL_CAND  0        // u64[CAP] = 64KB
#define SEL_HIST2 65536    // u32[2048]
#define SEL_SCN2  73728    // u32[2048]
#define SEL_SMEM  81920
__global__ void __launch_bounds__(1024) k_sel() {
    const int b = blockIdx.x, tid = threadIdx.x;
    if (g_T64[b] != 0ull) { if (tid == 0) g_ccnt[b] = 0u; return; }
    extern __shared__ unsigned char smraw[];
    unsigned long long* cand  = (unsigned long long*)(smraw + SEL_CAND);
    unsigned*           hist2 = (unsigned*)(smraw + SEL_HIST2);
    unsigned*           scn2  = (unsigned*)(smraw + SEL_SCN2);
    __shared__ unsigned s_ctrl[4];
    __shared__ unsigned long long s_T64;

    const unsigned* encb = g_enc + b * NANCH;
    unsigned M0 = g_ccnt[b];
    unsigned need = g_need[b];
    unsigned C;
    if (M0 <= CAP) {
        C = M0;
        for (unsigned j = tid; j < C; j += 1024) cand[j] = g_cand[b * CAP + j];
        __syncthreads();
    } else {
        // rare: refine bucket over g_enc until candidates fit CAP, then compact
        unsigned long long prefix = (unsigned long long)g_bucket[b];
        int shift = 50;
        unsigned count = M0;
        while (count > CAP) {
            int w = (shift >= 11) ? 11 : shift;
            int s2 = shift - w;
            unsigned dmask = (1u << w) - 1u;
            for (int t = tid; t < 2048; t += 1024) hist2[t] = 0u;
            __syncthreads();
            for (int it = 0; it < 25; ++it) {
                int i = tid + it * 1024;
                if (i < NANCH) {
                    unsigned long long key =
                        ((unsigned long long)encb[i] << 32) | (unsigned)(~(unsigned)i);
                    if ((key >> shift) == prefix)
                        atomicAdd(&hist2[(unsigned)((key >> s2) & dmask)], 1u);
                }
            }
            __syncthreads();
            for (int t = tid; t < 2048; t += 1024) scn2[t] = hist2[t];
            __syncthreads();
            for (int d = 1; d < 2048; d <<= 1) {
                unsigned a0 = (tid + d < 2048) ? scn2[tid + d] : 0u;
                unsigned a1 = (tid + 1024 + d < 2048) ? scn2[tid + 1024 + d] : 0u;
                __syncthreads();
                scn2[tid] += a0; scn2[tid + 1024] += a1;
                __syncthreads();
            }
            #pragma unroll
            for (int q = 0; q < 2; ++q) {
                int d = tid + q * 1024;
                unsigned tot = scn2[d], gt = tot - hist2[d];
                if (gt < need && need <= tot) {
                    s_ctrl[0] = (unsigned)d;
                    s_ctrl[1] = need - gt;
                    s_ctrl[2] = hist2[d];
                }
            }
            __syncthreads();
            prefix = (prefix << w) | (unsigned long long)s_ctrl[0];
            need = s_ctrl[1]; count = s_ctrl[2]; shift = s2;
            __syncthreads();
        }
        if (tid == 0) s_ctrl[3] = 0u;
        __syncthreads();
        for (int it = 0; it < 25; ++it) {
            int i = tid + it * 1024;
            if (i < NANCH) {
                unsigned long long key =
                    ((unsigned long long)encb[i] << 32) | (unsigned)(~(unsigned)i);
                if ((key >> shift) == prefix) {
                    unsigned pos = atomicAdd(&s_ctrl[3], 1u);
                    if (pos < CAP) cand[pos] = key;
                }
            }
        }
        __syncthreads();
        C = s_ctrl[3];
    }
    // rank-by-count: the key with exactly (need-1) greater keys
    for (unsigned j = tid; j < C; j += 1024) {
        unsigned long long kj = cand[j];
        unsigned gt = 0;
        for (unsigned k = 0; k < C; ++k) gt += (cand[k] > kj);
        if (gt == need - 1) s_T64 = kj;
    }
    __syncthreads();
    if (tid == 0) { g_T64[b] = s_T64; g_ccnt[b] = 0u; }
}

// ---------------- K2d: collect the exactly-1000 keys >= T64 (grid-wide, unordered) ----------------
__global__ void __launch_bounds__(1024) k_coll() {
    const int b = blockIdx.y;
    const int i = blockIdx.x * 1024 + threadIdx.x;
    if (i >= NANCH) return;
    unsigned e = g_enc[b * NANCH + i];
    unsigned long long key = ((unsigned long long)e << 32) | (unsigned)(~(unsigned)i);
    if (key >= g_T64[b]) {
        unsigned pos = atomicAdd(&g_scnt[b], 1u);
        if (pos < KPAD) g_selk[b * KPAD + pos] = key;
    }
}

// ---------------- K3a: rank winners + gather + argmax, scatter by rank (grid 8x8) ----------------
__global__ void __launch_bounds__(1024) k_rankg(const float* __restrict__ x) {
    const int b = blockIdx.y, slice = blockIdx.x;
    const int tid = threadIdx.x, wid = tid >> 5, lane = tid & 31;
    __shared__ unsigned long long keys[KPAD];
    __shared__ int   srank[128];
    __shared__ int   sidxA[128];
    __shared__ float sscoreA[128];

    const int n = (int)min(g_scnt[b], (unsigned)KPAD);   // == TOPK
    keys[tid] = (tid < n) ? g_selk[b * KPAD + tid] : 0ull;
    __syncthreads();

    // rank = count of greater keys; 8 threads per winner, conflict-free strided scan
    const int wl = tid >> 3, sub = tid & 7;
    const int j = slice * 128 + wl;
    {
        unsigned cnt = 0;
        if (j < n) {
            const unsigned long long kj = keys[j];
            #pragma unroll 8
            for (int i = 0; i < 128; ++i) cnt += (keys[sub + (i << 3)] > kj);
        }
        cnt += __shfl_down_sync(0xffffffffu, cnt, 4, 8);
        cnt += __shfl_down_sync(0xffffffffu, cnt, 2, 8);
        cnt += __shfl_down_sync(0xffffffffu, cnt, 1, 8);
        if (sub == 0) {
            if (j < n) {
                unsigned long long kj = keys[j];
                unsigned e = (unsigned)(kj >> 32);
                unsigned u = (e & 0x80000000u) ? (e ^ 0x80000000u) : ~e;
                srank[wl]   = (int)cnt;
                sscoreA[wl] = __uint_as_float(u);
                sidxA[wl]   = (int)(~(unsigned)(kj & 0xffffffffull));
            } else { srank[wl] = -1; sidxA[wl] = -1; sscoreA[wl] = -1.0f; }
        }
    }
    __syncthreads();

    // warp-per-winner coalesced gather + argmax; scatter to rank position
    for (int w2 = wid; w2 < 128; w2 += 32) {
        int idxa = sidxA[w2];
        if (idxa < 0) continue;
        const float* p = x + ((size_t)b * NANCH + idxa) * NCH;
        float v0 = p[lane];
        float v1 = p[32 + lane];
        float v2 = (lane < 21) ? p[64 + lane] : 0.0f;
        float best = __int_as_float(0xff800000);
        int   bi   = 1 << 30;
        if (lane >= 5)              { best = v0; bi = lane - 5;  }
        if (v1 > best)              { best = v1; bi = 27 + lane; }
        if (lane < 21 && v2 > best) { best = v2; bi = 59 + lane; }
        #pragma unroll
        for (int o = 16; o; o >>= 1) {
            float ov = __shfl_down_sync(0xffffffffu, best, o);
            int   oi = __shfl_down_sync(0xffffffffu, bi, o);
            if (ov > best || (ov == best && oi < bi)) { best = ov; bi = oi; }
        }
        float cx = __shfl_sync(0xffffffffu, v0, 0);
        float cy = __shfl_sync(0xffffffffu, v0, 1);
        float w  = __shfl_sync(0xffffffffu, v0, 2);
        float h  = __shfl_sync(0xffffffffu, v0, 3);
        if (lane == 0) {
            float hw = __fmul_rn(w, 0.5f), hh = __fmul_rn(h, 0.5f);
            float x1 = __fsub_rn(cx, hw), y1 = __fsub_rn(cy, hh);
            float x2 = __fadd_rn(cx, hw), y2 = __fadd_rn(cy, hh);
            float cf = (float)bi;
            float o2 = __fmul_rn(cf, MAX_WH);
            float ox1 = __fadd_rn(x1, o2), oy1 = __fadd_rn(y1, o2);
            float ox2 = __fadd_rn(x2, o2), oy2 = __fadd_rn(y2, o2);
            int r = b * KPAD + srank[w2];
            g_rboxp[r]  = make_float4(x1, y1, x2, y2);
            g_rboxo[r]  = make_float4(ox1, oy1, ox2, oy2);
            g_rarea[r]  = __fmul_rn(__fsub_rn(ox2, ox1), __fsub_rn(oy2, oy1));
            g_rcls[r]   = bi;
            g_rscore[r] = sscoreA[w2];
        }
    }
}

// ---------------- K3b: class-decomposed greedy NMS + output (grid 8) ----------------
#define NO_BOXO  0                       // float4[KPAD]
#define NO_AREA  (NO_BOXO + KPAD*16)     // float[KPAD]
#define NO_SCORE (NO_AREA + KPAD*4)
#define NO_SCLS  (NO_SCORE + KPAD*4)
#define NO_CLIST (NO_SCLS + KPAD*4)
#define NO_KL    (NO_CLIST + KPAD*4)
#define NO_KEEPW (NO_KL + KPAD*4)        // u32[32]
#define NO_CBIT  (NO_KEEPW + 128)        // u32[NCLS*32]
#define NO_CBASE (NO_CBIT + NCLS*32*4)   // int[NCLS+1]
#define NO_SMEM  (NO_CBASE + 512)

__global__ void __launch_bounds__(1024) k_nmsout(float* __restrict__ out) {
    const int b = blockIdx.x, tid = threadIdx.x;
    const int wid = tid >> 5, lane = tid & 31;
    extern __shared__ unsigned char sm[];
    float4*   boxo  = (float4*)  (sm + NO_BOXO);
    float*    area  = (float*)   (sm + NO_AREA);
    float*    score = (float*)   (sm + NO_SCORE);
    int*      scl   = (int*)     (sm + NO_SCLS);
    int*      clist = (int*)     (sm + NO_CLIST);
    int*      kl    = (int*)     (sm + NO_KL);
    unsigned* keepw = (unsigned*)(sm + NO_KEEPW);
    unsigned* cbit  = (unsigned*)(sm + NO_CBIT);
    int*      cbase = (int*)     (sm + NO_CBASE);

    // load rank-ordered data (coalesced)
    float sc = (tid < TOPK) ? g_rscore[b * KPAD + tid] : -1.0f;
    score[tid] = sc;
    boxo[tid]  = (tid < TOPK) ? g_rboxo[b * KPAD + tid] : make_float4(0.f,0.f,0.f,0.f);
    area[tid]  = (tid < TOPK) ? g_rarea[b * KPAD + tid] : 0.f;
    int cr     = (tid < TOPK) ? g_rcls [b * KPAD + tid] : -1;
    const int c = (tid < TOPK && sc > CONF_TH) ? cr : -1;
    scl[tid] = c;
    if (tid < 32) keepw[tid] = 0u;
    for (int t = tid; t < NCLS * 32; t += 1024) cbit[t] = 0u;
    if (tid < NCLS + 1) cbase[tid] = 0;
    __syncthreads();

    // per-class ordered member lists via bitmask + popcount ranks
    if (c >= 0) atomicOr(&cbit[c * 32 + (tid >> 5)], 1u << lane);
    __syncthreads();
    if (tid < NCLS) {
        unsigned cnt = 0;
        #pragma unroll 8
        for (int w = 0; w < 32; ++w) cnt += __popc(cbit[tid * 32 + w]);
        cbase[tid + 1] = (int)cnt;
    }
    __syncthreads();
    if (tid == 0) {
        int run = 0;
        #pragma unroll
        for (int k = 0; k < NCLS; ++k) { int t = cbase[k + 1]; cbase[k] = run; run += t; cbase[k + 1] = run; }
    }
    __syncthreads();
    if (c >= 0) {
        const int w0 = tid >> 5;
        unsigned r = 0;
        for (int w = 0; w < w0; ++w) r += __popc(cbit[c * 32 + w]);
        r += __popc(cbit[c * 32 + w0] & ((1u << lane) - 1u));
        clist[cbase[c] + r] = tid;
    }
    __syncthreads();

    // warp-per-class greedy with kept-list (fused IoU, reference fp32 arithmetic)
    for (int cc = wid; cc < NCLS; cc += 32) {
        int base = cbase[cc], m = cbase[cc + 1] - base;
        int nk = 0;
        for (int k = 0; k < m; ++k) {
            int j = clist[base + k];
            float4 bj = boxo[j];
            float  aj = area[j];
            bool sup = false;
            for (int q = lane; q < nk; q += 32) {
                int jk = kl[base + q];
                float4 bk = boxo[jk];
                float ww = fmaxf(__fsub_rn(fminf(bk.z, bj.z), fmaxf(bk.x, bj.x)), 0.0f);
                float hh = fmaxf(__fsub_rn(fminf(bk.w, bj.w), fmaxf(bk.y, bj.y)), 0.0f);
                float inter = __fmul_rn(ww, hh);
                float den = __fadd_rn(__fsub_rn(__fadd_rn(area[jk], aj), inter), 1e-9f);
                if (__fdiv_rn(inter, den) > IOU_TH) sup = true;
            }
            sup = __any_sync(0xffffffffu, sup);
            if (!sup) {
                if (lane == 0) { kl[base + nk] = j; atomicOr(&keepw[j >> 5], 1u << (j & 31)); }
                nk++;
                __syncwarp();
            }
        }
    }
    __syncthreads();

    // output
    if (tid < TOPK) {
        bool keep = (keepw[tid >> 5] >> (tid & 31)) & 1u;
        float4 bx = g_rboxp[b * KPAD + tid];
        float so  = score[tid];
        float cf  = (float)((scl[tid] >= 0) ? scl[tid] : g_rcls[b * KPAD + tid]);
        if (!keep) { bx = make_float4(0.f, 0.f, 0.f, 0.f); so = 0.f; cf = 0.f; }
        float* o = out + ((size_t)b * TOPK + tid) * 6;
        o[0] = bx.x; o[1] = bx.y; o[2] = bx.z; o[3] = bx.w; o[4] = so; o[5] = cf;
    }
    if (tid == 0) g_scnt[b] = 0u;   // self-clean for next replay
}

// ---------------- launcher ----------------
extern "C" void kernel_launch(void* const* d_in, const int* in_sizes, int n_in,
                              void* d_out, int out_size) {
    (void)in_sizes; (void)n_in; (void)out_size;
    const float* x = (const float*)d_in[0];
    float* out = (float*)d_out;
    cudaFuncSetAttribute(k_sel,    cudaFuncAttributeMaxDynamicSharedMemorySize, SEL_SMEM);
    cudaFuncSetAttribute(k_nmsout, cudaFuncAttributeMaxDynamicSharedMemorySize, NO_SMEM);

    k_score <<<(BATCH * NANCH) / SB, SB>>>(x);
    k_pick  <<<BATCH, 1024>>>();
    k_cand  <<<dim3(25, BATCH), 1024>>>();
    k_sel   <<<BATCH, 1024, SEL_SMEM>>>();
    k_coll  <<<dim3(25, BATCH), 1024>>>();
    k_rankg <<<dim3(8, BATCH), 1024>>>(x);
    k_nmsout<<<BATCH, 1024, NO_SMEM>>>(out);
}

// round 17
// speedup vs baseline: 1.4385x; 1.3055x over previous
#include <cuda_runtime.h>
#include <cstdint>

#define BATCH   8
#define NANCH   25200
#define NCH     85
#define TOPK    1000
#define KPAD    1024
#define NCLS    80
#define CGRP    10     // classes per k_nmscls block
#define CONF_TH 0.25f
#define IOU_TH  0.45f
#define MAX_WH  4096.0f
#define NB14    16384
#define CAP     8192

// ---------------- scratch (device globals; no allocation) ----------------
__device__ unsigned           g_enc [BATCH * NANCH];
__device__ unsigned           g_hist[BATCH * NB14];   // zeroed by k_pick after use
__device__ unsigned long long g_cand[BATCH * CAP];
__device__ unsigned long long g_selk[BATCH * KPAD];
__device__ unsigned           g_ccnt[BATCH];          // zeroed by k_out after use
__device__ unsigned           g_scnt[BATCH];          // zeroed by k_out after use
__device__ unsigned           g_bucket[BATCH];
__device__ unsigned           g_need[BATCH];
__device__ unsigned long long g_T64[BATCH];           // written by k_pick each run
__device__ unsigned           g_keep[BATCH * 32];     // zeroed by k_pick each run
// rank-ordered winner data (rows [0,TOPK) rewritten every run)
__device__ float  g_rscore[BATCH * KPAD];
__device__ float4 g_rboxp [BATCH * KPAD];
__device__ float4 g_rboxo [BATCH * KPAD];
__device__ float  g_rarea [BATCH * KPAD];
__device__ int    g_rcls  [BATCH * KPAD];

// ---------------- K1: score = obj * max(cls); encode; fused 14-bit histogram ----------------
#define SB 128
__global__ void __launch_bounds__(SB) k_score(const float* __restrict__ x) {
    __shared__ float sx[SB * NCH];
    const int tid = threadIdx.x;
    const size_t base = (size_t)blockIdx.x * SB * NCH;
    const float4* xv = (const float4*)(x + base);
    float4* sv = (float4*)sx;
    #pragma unroll
    for (int t = tid; t < SB * NCH / 4; t += SB) sv[t] = xv[t];
    __syncthreads();

    const int a = blockIdx.x * SB + tid;
    const float* p = sx + tid * NCH;
    const float obj = p[4];

    const int off = tid * NCH + 5;
    const int pre = (-off) & 3;
    float m0 = __int_as_float(0xff800000);
    for (int k = 0; k < pre; ++k) m0 = fmaxf(m0, sx[off + k]);
    const int a0  = off + pre;
    const int n   = 80 - pre;
    const int nf4 = n >> 2;
    const int tl  = n & 3;
    const float4* pv = (const float4*)(sx + a0);
    float4 acc = pv[0];
    #pragma unroll 4
    for (int q = 1; q < nf4; ++q) {
        float4 v = pv[q];
        acc.x = fmaxf(acc.x, v.x); acc.y = fmaxf(acc.y, v.y);
        acc.z = fmaxf(acc.z, v.z); acc.w = fmaxf(acc.w, v.w);
    }
    float m = fmaxf(fmaxf(acc.x, acc.y), fmaxf(acc.z, acc.w));
    m = fmaxf(m, m0);
    const int tb = a0 + 4 * nf4;
    for (int k = 0; k < tl; ++k) m = fmaxf(m, sx[tb + k]);

    float sc = __fmul_rn(obj, m);
    unsigned u = __float_as_uint((sc > CONF_TH) ? sc : -1.0f);
    unsigned e = (u & 0x80000000u) ? ~u : (u | 0x80000000u);
    g_enc[a] = e;

    int b = a / NANCH;
    unsigned addr = (unsigned)b * NB14 + (e >> 18);
    unsigned mm = __match_any_sync(0xffffffffu, addr);
    if ((tid & 31) == (__ffs(mm) - 1))
        atomicAdd(&g_hist[addr], (unsigned)__popc(mm));
}

// ---------------- K2a: boundary bucket via register suffix scan; zero keep mask ----------------
__global__ void __launch_bounds__(1024) k_pick() {
    const int b = blockIdx.x, tid = threadIdx.x;
    const int wid = tid >> 5, lane = tid & 31;
    __shared__ unsigned s_w[32];

    if (tid < 32) g_keep[b * 32 + tid] = 0u;   // zero keep mask for this run

    unsigned lv[16];
    const uint4* hv = (const uint4*)(g_hist + b * NB14 + tid * 16);
    #pragma unroll
    for (int q = 0; q < 4; ++q) {
        uint4 h = hv[q];
        lv[q * 4 + 0] = h.x; lv[q * 4 + 1] = h.y;
        lv[q * 4 + 2] = h.z; lv[q * 4 + 3] = h.w;
    }
    uint4* hz = (uint4*)(g_hist + b * NB14 + tid * 16);
    const uint4 z4 = make_uint4(0u, 0u, 0u, 0u);
    #pragma unroll
    for (int q = 0; q < 4; ++q) hz[q] = z4;

    unsigned run = 0;
    #pragma unroll
    for (int i = 15; i >= 0; --i) { run += lv[i]; lv[i] = run; }
    const unsigned ttot = run;
    unsigned v = ttot;
    #pragma unroll
    for (int off = 1; off < 32; off <<= 1) {
        unsigned t = __shfl_down_sync(0xffffffffu, v, off);
        if (lane + off < 32) v += t;
    }
    if (lane == 0) s_w[wid] = v;
    __syncthreads();
    if (tid < 32) {
        unsigned u0 = s_w[tid], w = u0;
        #pragma unroll
        for (int off = 1; off < 32; off <<= 1) {
            unsigned t = __shfl_down_sync(0xffffffffu, w, off);
            if (tid + off < 32) w += t;
        }
        s_w[tid] = w - u0;
    }
    __syncthreads();
    {
        const int base16 = tid * 16;
        unsigned above = s_w[wid] + (v - ttot);
        #pragma unroll
        for (int i = 0; i < 16; ++i) {
            unsigned tot = above + lv[i];
            unsigned cnt = lv[i] - ((i < 15) ? lv[i + 1] : 0u);
            unsigned gt  = tot - cnt;
            if (gt < TOPK && TOPK <= tot) {
                unsigned need = TOPK - gt;
                g_bucket[b] = (unsigned)(base16 + i);
                g_need[b]   = need;
                g_T64[b]    = (need == cnt)
                              ? ((unsigned long long)(base16 + i) << 50) : 0ull;
            }
        }
    }
}

// ---------------- K2b: compact boundary-bucket candidates (grid-wide) ----------------
__global__ void __launch_bounds__(1024) k_cand() {
    const int b = blockIdx.y;
    if (g_T64[b] != 0ull) return;
    const int i = blockIdx.x * 1024 + threadIdx.x;
    if (i >= NANCH) return;
    unsigned e = g_enc[b * NANCH + i];
    if ((e >> 18) == g_bucket[b]) {
        unsigned pos = atomicAdd(&g_ccnt[b], 1u);
        if (pos < CAP)
            g_cand[b * CAP + pos] =
                ((unsigned long long)e << 32) | (unsigned)(~(unsigned)i);
    }
}

// ---------------- K2c: exact 1000th key, sliced rank-by-count (grid 64x8) ----------------
#define SEL_SMEM  (CAP * 8 + 16384 + 64)   // keys u64[CAP] | hist2/scn2 overlap region
__global__ void __launch_bounds__(1024) k_sel2() {
    const int b = blockIdx.y, slice = blockIdx.x;
    const int tid = threadIdx.x;
    if (g_T64[b] != 0ull) return;
    extern __shared__ unsigned char smraw[];
    unsigned long long* keys  = (unsigned long long*)smraw;
    unsigned*           hist2 = (unsigned*)(smraw + CAP * 8);
    unsigned*           scn2  = (unsigned*)(smraw + CAP * 8 + 8192);
    __shared__ unsigned s_ctrl[4];

    const unsigned M0 = g_ccnt[b];
    unsigned need = g_need[b];

    if (M0 <= CAP) {
        const unsigned C = M0;
        if ((unsigned)(slice * 128) >= C) return;
        for (unsigned j = tid; j < C; j += 1024) keys[j] = g_cand[b * CAP + j];
        __syncthreads();
        const int wl = tid >> 3, sub = tid & 7;
        const unsigned j = (unsigned)(slice * 128 + wl);
        unsigned cnt = 0;
        if (j < C) {
            const unsigned long long kj = keys[j];
            for (unsigned i = (unsigned)sub; i < C; i += 8) cnt += (keys[i] > kj);
        }
        cnt += __shfl_down_sync(0xffffffffu, cnt, 4, 8);
        cnt += __shfl_down_sync(0xffffffffu, cnt, 2, 8);
        cnt += __shfl_down_sync(0xffffffffu, cnt, 1, 8);
        if (sub == 0 && j < C && cnt == need - 1) g_T64[b] = keys[j];
        return;
    }

    // rare fallback (C > CAP): slice 0 runs the serial refinement
    if (slice != 0) return;
    const unsigned* encb = g_enc + b * NANCH;
    unsigned long long prefix = (unsigned long long)g_bucket[b];
    int shift = 50;
    unsigned count = M0;
    while (count > CAP) {
        int w = (shift >= 11) ? 11 : shift;
        int s2 = shift - w;
        unsigned dmask = (1u << w) - 1u;
        for (int t = tid; t < 2048; t += 1024) hist2[t] = 0u;
        __syncthreads();
        for (int it = 0; it < 25; ++it) {
            int i = tid + it * 1024;
            if (i < NANCH) {
                unsigned long long key =
                    ((unsigned long long)encb[i] << 32) | (unsigned)(~(unsigned)i);
                if ((key >> shift) == prefix)
                    atomicAdd(&hist2[(unsigned)((key >> s2) & dmask)], 1u);
            }
        }
        __syncthreads();
        for (int t = tid; t < 2048; t += 1024) scn2[t] = hist2[t];
        __syncthreads();
        for (int d = 1; d < 2048; d <<= 1) {
            unsigned a0 = (tid + d < 2048) ? scn2[tid + d] : 0u;
            unsigned a1 = (tid + 1024 + d < 2048) ? scn2[tid + 1024 + d] : 0u;
            __syncthreads();
            scn2[tid] += a0; scn2[tid + 1024] += a1;
            __syncthreads();
        }
        #pragma unroll
        for (int q = 0; q < 2; ++q) {
            int d = tid + q * 1024;
            unsigned tot = scn2[d], gt = tot - hist2[d];
            if (gt < need && need <= tot) {
                s_ctrl[0] = (unsigned)d;
                s_ctrl[1] = need - gt;
                s_ctrl[2] = hist2[d];
            }
        }
        __syncthreads();
        prefix = (prefix << w) | (unsigned long long)s_ctrl[0];
        need = s_ctrl[1]; count = s_ctrl[2]; shift = s2;
        __syncthreads();
    }
    if (tid == 0) s_ctrl[3] = 0u;
    __syncthreads();
    for (int it = 0; it < 25; ++it) {
        int i = tid + it * 1024;
        if (i < NANCH) {
            unsigned long long key =
                ((unsigned long long)encb[i] << 32) | (unsigned)(~(unsigned)i);
            if ((key >> shift) == prefix) {
                unsigned pos = atomicAdd(&s_ctrl[3], 1u);
                if (pos < CAP) keys[pos] = key;
            }
        }
    }
    __syncthreads();
    const unsigned C = s_ctrl[3];
    for (unsigned j = tid; j < C; j += 1024) {
        unsigned long long kj = keys[j];
        unsigned gt = 0;
        for (unsigned k = 0; k < C; ++k) gt += (keys[k] > kj);
        if (gt == need - 1) g_T64[b] = kj;
    }
}

// ---------------- K2d: collect the exactly-1000 keys >= T64 (grid-wide, unordered) ----------------
__global__ void __launch_bounds__(1024) k_coll() {
    const int b = blockIdx.y;
    const int i = blockIdx.x * 1024 + threadIdx.x;
    if (i >= NANCH) return;
    unsigned e = g_enc[b * NANCH + i];
    unsigned long long key = ((unsigned long long)e << 32) | (unsigned)(~(unsigned)i);
    if (key >= g_T64[b]) {
        unsigned pos = atomicAdd(&g_scnt[b], 1u);
        if (pos < KPAD) g_selk[b * KPAD + pos] = key;
    }
}

// ---------------- K3a: rank winners + gather + argmax, scatter by rank (grid 8x8) ----------------
__global__ void __launch_bounds__(1024) k_rankg(const float* __restrict__ x) {
    const int b = blockIdx.y, slice = blockIdx.x;
    const int tid = threadIdx.x, wid = tid >> 5, lane = tid & 31;
    __shared__ unsigned long long keys[KPAD];
    __shared__ int   srank[128];
    __shared__ int   sidxA[128];
    __shared__ float sscoreA[128];

    const int n = (int)min(g_scnt[b], (unsigned)KPAD);   // == TOPK
    keys[tid] = (tid < n) ? g_selk[b * KPAD + tid] : 0ull;
    __syncthreads();

    const int wl = tid >> 3, sub = tid & 7;
    const int j = slice * 128 + wl;
    {
        unsigned cnt = 0;
        if (j < n) {
            const unsigned long long kj = keys[j];
            #pragma unroll 8
            for (int i = 0; i < 128; ++i) cnt += (keys[sub + (i << 3)] > kj);
        }
        cnt += __shfl_down_sync(0xffffffffu, cnt, 4, 8);
        cnt += __shfl_down_sync(0xffffffffu, cnt, 2, 8);
        cnt += __shfl_down_sync(0xffffffffu, cnt, 1, 8);
        if (sub == 0) {
            if (j < n) {
                unsigned long long kj = keys[j];
                unsigned e = (unsigned)(kj >> 32);
                unsigned u = (e & 0x80000000u) ? (e ^ 0x80000000u) : ~e;
                srank[wl]   = (int)cnt;
                sscoreA[wl] = __uint_as_float(u);
                sidxA[wl]   = (int)(~(unsigned)(kj & 0xffffffffull));
            } else { srank[wl] = -1; sidxA[wl] = -1; sscoreA[wl] = -1.0f; }
        }
    }
    __syncthreads();

    for (int w2 = wid; w2 < 128; w2 += 32) {
        int idxa = sidxA[w2];
        if (idxa < 0) continue;
        const float* p = x + ((size_t)b * NANCH + idxa) * NCH;
        float v0 = p[lane];
        float v1 = p[32 + lane];
        float v2 = (lane < 21) ? p[64 + lane] : 0.0f;
        float best = __int_as_float(0xff800000);
        int   bi   = 1 << 30;
        if (lane >= 5)              { best = v0; bi = lane - 5;  }
        if (v1 > best)              { best = v1; bi = 27 + lane; }
        if (lane < 21 && v2 > best) { best = v2; bi = 59 + lane; }
        #pragma unroll
        for (int o = 16; o; o >>= 1) {
            float ov = __shfl_down_sync(0xffffffffu, best, o);
            int   oi = __shfl_down_sync(0xffffffffu, bi, o);
            if (ov > best || (ov == best && oi < bi)) { best = ov; bi = oi; }
        }
        float cx = __shfl_sync(0xffffffffu, v0, 0);
        float cy = __shfl_sync(0xffffffffu, v0, 1);
        float w  = __shfl_sync(0xffffffffu, v0, 2);
        float h  = __shfl_sync(0xffffffffu, v0, 3);
        if (lane == 0) {
            float hw = __fmul_rn(w, 0.5f), hh = __fmul_rn(h, 0.5f);
            float x1 = __fsub_rn(cx, hw), y1 = __fsub_rn(cy, hh);
            float x2 = __fadd_rn(cx, hw), y2 = __fadd_rn(cy, hh);
            float cf = (float)bi;
            float o2 = __fmul_rn(cf, MAX_WH);
            float ox1 = __fadd_rn(x1, o2), oy1 = __fadd_rn(y1, o2);
            float ox2 = __fadd_rn(x2, o2), oy2 = __fadd_rn(y2, o2);
            int r = b * KPAD + srank[w2];
            g_rboxp[r]  = make_float4(x1, y1, x2, y2);
            g_rboxo[r]  = make_float4(ox1, oy1, ox2, oy2);
            g_rarea[r]  = __fmul_rn(__fsub_rn(ox2, ox1), __fsub_rn(oy2, oy1));
            g_rcls[r]   = bi;
            g_rscore[r] = sscoreA[w2];
        }
    }
}

// ---------------- K3b: class-group greedy NMS (grid 8x8), keep -> g_keep ----------------
__global__ void __launch_bounds__(1024) k_nmscls() {
    const int b = blockIdx.y, grp = blockIdx.x;
    const int c0 = grp * CGRP;
    const int tid = threadIdx.x, wid = tid >> 5, lane = tid & 31;
    __shared__ float4 boxo[KPAD];
    __shared__ float  area[KPAD];
    __shared__ int    clist[KPAD];
    __shared__ int    kl[KPAD];
    __shared__ unsigned cbit[CGRP * 32];
    __shared__ int    cbase[CGRP + 1];

    float sc = (tid < TOPK) ? g_rscore[b * KPAD + tid] : -1.0f;
    int   cr = (tid < TOPK) ? g_rcls [b * KPAD + tid] : -1;
    boxo[tid] = (tid < TOPK) ? g_rboxo[b * KPAD + tid] : make_float4(0.f,0.f,0.f,0.f);
    area[tid] = (tid < TOPK) ? g_rarea[b * KPAD + tid] : 0.f;
    int lc = -1;
    if (tid < TOPK && sc > CONF_TH && cr >= c0 && cr < c0 + CGRP) lc = cr - c0;
    for (int t = tid; t < CGRP * 32; t += 1024) cbit[t] = 0u;
    if (tid < CGRP + 1) cbase[tid] = 0;
    __syncthreads();

    if (lc >= 0) atomicOr(&cbit[lc * 32 + (tid >> 5)], 1u << lane);
    __syncthreads();
    if (tid < CGRP) {
        unsigned cnt = 0;
        #pragma unroll 8
        for (int w = 0; w < 32; ++w) cnt += __popc(cbit[tid * 32 + w]);
        cbase[tid + 1] = (int)cnt;
    }
    __syncthreads();
    if (tid == 0) {
        int run = 0;
        #pragma unroll
        for (int k = 0; k < CGRP; ++k) { int t = cbase[k + 1]; cbase[k] = run; run += t; cbase[k + 1] = run; }
    }
    __syncthreads();
    if (lc >= 0) {
        const int w0 = tid >> 5;
        unsigned r = 0;
        for (int w = 0; w < w0; ++w) r += __popc(cbit[lc * 32 + w]);
        r += __popc(cbit[lc * 32 + w0] & ((1u << lane) - 1u));
        clist[cbase[lc] + r] = tid;
    }
    __syncthreads();

    // warp-per-class greedy with kept-list (reference fp32 arithmetic)
    if (wid < CGRP) {
        const int cc = wid;
        int base = cbase[cc], m = cbase[cc + 1] - base;
        int nk = 0;
        for (int k = 0; k < m; ++k) {
            int j = clist[base + k];
            float4 bj = boxo[j];
            float  aj = area[j];
            bool sup = false;
            for (int q = lane; q < nk; q += 32) {
                int jk = kl[base + q];
                float4 bk = boxo[jk];
                float ww = fmaxf(__fsub_rn(fminf(bk.z, bj.z), fmaxf(bk.x, bj.x)), 0.0f);
                float hh = fmaxf(__fsub_rn(fminf(bk.w, bj.w), fmaxf(bk.y, bj.y)), 0.0f);
                float inter = __fmul_rn(ww, hh);
                float den = __fadd_rn(__fsub_rn(__fadd_rn(area[jk], aj), inter), 1e-9f);
                if (__fdiv_rn(inter, den) > IOU_TH) sup = true;
            }
            sup = __any_sync(0xffffffffu, sup);
            if (!sup) {
                if (lane == 0) { kl[base + nk] = j; atomicOr(&g_keep[b * 32 + (j >> 5)], 1u << (j & 31)); }
                nk++;
                __syncwarp();
            }
        }
    }
}

// ---------------- K4: output + self-clean (grid 8) ----------------
__global__ void __launch_bounds__(1024) k_out(float* __restrict__ out) {
    const int b = blockIdx.x, tid = threadIdx.x;
    __shared__ unsigned keepw[32];
    if (tid < 32) keepw[tid] = g_keep[b * 32 + tid];
    __syncthreads();
    if (tid < TOPK) {
        bool keep = (keepw[tid >> 5] >> (tid & 31)) & 1u;
        float4 bx = g_rboxp[b * KPAD + tid];
        float so  = g_rscore[b * KPAD + tid];
        float cf  = (float)g_rcls[b * KPAD + tid];
        if (!keep) { bx = make_float4(0.f, 0.f, 0.f, 0.f); so = 0.f; cf = 0.f; }
        float* o = out + ((size_t)b * TOPK + tid) * 6;
        o[0] = bx.x; o[1] = bx.y; o[2] = bx.z; o[3] = bx.w; o[4] = so; o[5] = cf;
    }
    if (tid == 0) { g_scnt[b] = 0u; g_ccnt[b] = 0u; }
}

// ---------------- launcher ----------------
extern "C" void kernel_launch(void* const* d_in, const int* in_sizes, int n_in,
                              void* d_out, int out_size) {
    (void)in_sizes; (void)n_in; (void)out_size;
    const float* x = (const float*)d_in[0];
    float* out = (float*)d_out;
    cudaFuncSetAttribute(k_sel2, cudaFuncAttributeMaxDynamicSharedMemorySize, SEL_SMEM);

    k_score <<<(BATCH * NANCH) / SB, SB>>>(x);
    k_pick  <<<BATCH, 1024>>>();
    k_cand  <<<dim3(25, BATCH), 1024>>>();
    k_sel2  <<<dim3(64, BATCH), 1024, SEL_SMEM>>>();
    k_coll  <<<dim3(25, BATCH), 1024>>>();
    k_rankg <<<dim3(8, BATCH), 1024>>>(x);
    k_nmscls<<<dim3(8, BATCH), 1024>>>();
    k_out   <<<BATCH, 1024>>>(out);
}